// round 1
// baseline (speedup 1.0000x reference)
#include <cuda_runtime.h>

#define BB   32
#define CHN  16
#define NN   261
#define KW   6
#define MM   256
#define MAT  (MM*MM)
#define NMAT (BB*CHN)

// Scratch (device globals: no allocation allowed in kernel_launch)
__device__ float g_feat[NMAT * MAT];   // 128 MB: conv features, [bc][row][col]
__device__ float g_B2[NMAT * MAT];     // 128 MB: A^2 per matrix
__device__ float g_part[NMAT * 4 * 4]; // [bc][tile 0..3][trace k 0..3] deterministic partials

// ---------------------------------------------------------------------------
// Conv: x[b,261,261] * w[16,1,6,6] -> feat[b*16+c, 256,256]  (VALID, corr)
// 32x32 output tile per block, 256 threads (32x8), each thread 4 rows x 16 ch
// ---------------------------------------------------------------------------
__global__ void __launch_bounds__(256) conv_kernel(const float* __restrict__ x,
                                                   const float* __restrict__ w,
                                                   const float* __restrict__ bias) {
    __shared__ float xs[37][38];
    __shared__ float ws[CHN * 36];
    __shared__ float bs[CHN];
    const int b  = blockIdx.z;
    const int bx = blockIdx.x * 32, by = blockIdx.y * 32;
    const int tx = threadIdx.x, ty = threadIdx.y;
    const int tid = ty * 32 + tx;

    for (int i = tid; i < 37 * 37; i += 256) {
        int r = i / 37, c = i % 37;
        xs[r][c] = x[b * NN * NN + (by + r) * NN + (bx + c)];
    }
    for (int i = tid; i < CHN * 36; i += 256) ws[i] = w[i];
    if (tid < CHN) bs[tid] = bias[tid];
    __syncthreads();

    float acc[4][CHN];
#pragma unroll
    for (int r = 0; r < 4; r++)
#pragma unroll
        for (int c = 0; c < CHN; c++) acc[r][c] = bs[c];

#pragma unroll
    for (int p = 0; p < KW; p++) {
#pragma unroll
        for (int q = 0; q < KW; q++) {
            float xv[4];
#pragma unroll
            for (int r = 0; r < 4; r++) xv[r] = xs[ty + 8 * r + p][tx + q];
#pragma unroll
            for (int c = 0; c < CHN; c++) {
                float wv = ws[c * 36 + p * 6 + q];
#pragma unroll
                for (int r = 0; r < 4; r++) acc[r][c] += xv[r] * wv;
            }
        }
    }

#pragma unroll
    for (int c = 0; c < CHN; c++) {
#pragma unroll
        for (int r = 0; r < 4; r++) {
            int row = by + ty + 8 * r, col = bx + tx;
            g_feat[(b * CHN + c) * MAT + row * MM + col] = acc[r][c];
        }
    }
}

// ---------------------------------------------------------------------------
// SGEMM core: C(128x128 tile) = A * B for one 256x256 matrix (blockIdx.z)
// BM=BN=128, BK=8, 256 threads, 8x8 microtile.
// ---------------------------------------------------------------------------
__global__ void __launch_bounds__(256) gemm_b2_kernel() {
    __shared__ float As[8][128];
    __shared__ float Bs[8][128];
    const int bc = blockIdx.z;
    const float* A = g_feat + bc * MAT;
    const float* B = g_feat + bc * MAT;
    const int rowBase = blockIdx.y * 128;
    const int colBase = blockIdx.x * 128;
    const int tid = threadIdx.x;
    const int irA = tid >> 1, icA = (tid & 1) * 4;
    const int irB = tid >> 5, icB = (tid & 31) * 4;
    const int tRow = (tid >> 4) * 8, tCol = (tid & 15) * 8;

    float acc[8][8] = {};
    for (int kb = 0; kb < MM; kb += 8) {
        float4 a4 = *(const float4*)(A + (rowBase + irA) * MM + kb + icA);
        As[icA + 0][irA] = a4.x; As[icA + 1][irA] = a4.y;
        As[icA + 2][irA] = a4.z; As[icA + 3][irA] = a4.w;
        *(float4*)(&Bs[irB][icB]) = *(const float4*)(B + (kb + irB) * MM + colBase + icB);
        __syncthreads();
#pragma unroll
        for (int k = 0; k < 8; k++) {
            float rm[8], rn[8];
            *(float4*)(rm)     = *(float4*)(&As[k][tRow]);
            *(float4*)(rm + 4) = *(float4*)(&As[k][tRow + 4]);
            *(float4*)(rn)     = *(float4*)(&Bs[k][tCol]);
            *(float4*)(rn + 4) = *(float4*)(&Bs[k][tCol + 4]);
#pragma unroll
            for (int i = 0; i < 8; i++)
#pragma unroll
                for (int j = 0; j < 8; j++) acc[i][j] += rm[i] * rn[j];
        }
        __syncthreads();
    }

    float* C = g_B2 + bc * MAT;
#pragma unroll
    for (int i = 0; i < 8; i++) {
        int row = rowBase + tRow + i;
#pragma unroll
        for (int j = 0; j < 8; j += 4)
            *(float4*)(C + row * MM + colBase + tCol + j) = *(float4*)(&acc[i][j]);
    }
}

// B3 = A * B2 (tile computed, never stored). Epilogue reduces:
//   k=0: tr(A^2)=sum diag B2      k=1: tr(A^3)=sum diag B3
//   k=2: tr(A^4)=sum B2ij*B2ji    k=3: tr(A^5)=sum B3ij*B2ji
__global__ void __launch_bounds__(256) gemm_b3_trace_kernel() {
    __shared__ float As[8][128];
    __shared__ float Bs[8][128];
    const int bc = blockIdx.z;
    const float* A = g_feat + bc * MAT;
    const float* B = g_B2 + bc * MAT;
    const int rowBase = blockIdx.y * 128;
    const int colBase = blockIdx.x * 128;
    const int tid = threadIdx.x;
    const int irA = tid >> 1, icA = (tid & 1) * 4;
    const int irB = tid >> 5, icB = (tid & 31) * 4;
    const int tRow = (tid >> 4) * 8, tCol = (tid & 15) * 8;

    float acc[8][8] = {};
    for (int kb = 0; kb < MM; kb += 8) {
        float4 a4 = *(const float4*)(A + (rowBase + irA) * MM + kb + icA);
        As[icA + 0][irA] = a4.x; As[icA + 1][irA] = a4.y;
        As[icA + 2][irA] = a4.z; As[icA + 3][irA] = a4.w;
        *(float4*)(&Bs[irB][icB]) = *(const float4*)(B + (kb + irB) * MM + colBase + icB);
        __syncthreads();
#pragma unroll
        for (int k = 0; k < 8; k++) {
            float rm[8], rn[8];
            *(float4*)(rm)     = *(float4*)(&As[k][tRow]);
            *(float4*)(rm + 4) = *(float4*)(&As[k][tRow + 4]);
            *(float4*)(rn)     = *(float4*)(&Bs[k][tCol]);
            *(float4*)(rn + 4) = *(float4*)(&Bs[k][tCol + 4]);
#pragma unroll
            for (int i = 0; i < 8; i++)
#pragma unroll
                for (int j = 0; j < 8; j++) acc[i][j] += rm[i] * rn[j];
        }
        __syncthreads();
    }

    // trace partials over this thread's 8x8 patch
    float p2 = 0.f, p3 = 0.f, p4 = 0.f, p5 = 0.f;
    const float* B2m = g_B2 + bc * MAT;
#pragma unroll
    for (int i = 0; i < 8; i++) {
        int row = rowBase + tRow + i;
#pragma unroll
        for (int j = 0; j < 8; j++) {
            int col = colBase + tCol + j;
            float b3  = acc[i][j];
            float b2t = __ldg(B2m + col * MM + row);   // B2[j,i]
            float b2  = __ldg(B2m + row * MM + col);   // B2[i,j]
            p5 += b3 * b2t;
            p4 += b2 * b2t;
            if (row == col) { p3 += b3; p2 += b2; }
        }
    }
    // warp reduce then block reduce (deterministic per-block partial)
#pragma unroll
    for (int off = 16; off; off >>= 1) {
        p2 += __shfl_down_sync(0xFFFFFFFFu, p2, off);
        p3 += __shfl_down_sync(0xFFFFFFFFu, p3, off);
        p4 += __shfl_down_sync(0xFFFFFFFFu, p4, off);
        p5 += __shfl_down_sync(0xFFFFFFFFu, p5, off);
    }
    __shared__ float red[8][4];
    int warp = tid >> 5, lane = tid & 31;
    if (lane == 0) { red[warp][0] = p2; red[warp][1] = p3; red[warp][2] = p4; red[warp][3] = p5; }
    __syncthreads();
    if (tid == 0) {
        float s[4] = {0.f, 0.f, 0.f, 0.f};
        for (int w2 = 0; w2 < 8; w2++)
            for (int k = 0; k < 4; k++) s[k] += red[w2][k];
        int tileIdx = blockIdx.y * 2 + blockIdx.x;
        for (int k = 0; k < 4; k++) g_part[(bc * 4 + tileIdx) * 4 + k] = s[k];
    }
}

// ---------------------------------------------------------------------------
// Combine: out[b] = sum_{c,i,j} coef[c,i,j] * tr[b,c,i]^(j+1) / (m^2)^(i+j+1)
// m^2 = 65536 = 2^16 -> exact ldexp scaling, accumulate in double.
// ---------------------------------------------------------------------------
__global__ void __launch_bounds__(512) final_kernel(const float* __restrict__ coef,
                                                    float* __restrict__ out) {
    int t = threadIdx.x;            // 0..511
    int b = t >> 4, c = t & 15;
    int bc = b * CHN + c;
    double tr[4];
#pragma unroll
    for (int k = 0; k < 4; k++) {
        float s = 0.f;
#pragma unroll
        for (int tile = 0; tile < 4; tile++) s += g_part[(bc * 4 + tile) * 4 + k];
        tr[k] = (double)s;
    }
    double sum = 0.0;
#pragma unroll
    for (int i = 0; i < 4; i++) {
        double p = tr[i];
        double tp = p;
#pragma unroll
        for (int j = 0; j < 4; j++) {
            double v = ldexp(tp, -16 * (i + j + 1));   // tr^(j+1) / 65536^(i+j+1)
            sum += (double)coef[c * 16 + i * 4 + j] * v;
            tp *= p;
        }
    }
    // reduce over the 16 channels living in the same half-warp
#pragma unroll
    for (int off = 8; off; off >>= 1)
        sum += __shfl_down_sync(0xFFFFFFFFu, sum, off, 16);
    if (c == 0) out[b] = (float)sum;
}

extern "C" void kernel_launch(void* const* d_in, const int* in_sizes, int n_in,
                              void* d_out, int out_size) {
    const float* x    = (const float*)d_in[0];  // [32,261,261]
    const float* w    = (const float*)d_in[1];  // [16,1,6,6]
    const float* bias = (const float*)d_in[2];  // [16]
    const float* coef = (const float*)d_in[3];  // [16,4,4]
    float* out = (float*)d_out;                 // [32]

    conv_kernel<<<dim3(8, 8, BB), dim3(32, 8)>>>(x, w, bias);
    gemm_b2_kernel<<<dim3(2, 2, NMAT), 256>>>();
    gemm_b3_trace_kernel<<<dim3(2, 2, NMAT), 256>>>();
    final_kernel<<<1, 512>>>(coef, out);
}

// round 3
// speedup vs baseline: 1.9543x; 1.9543x over previous
#include <cuda_runtime.h>
#include <cuda_bf16.h>
#include <cstdint>

#define BB   32
#define CHN  16
#define NN   261
#define MM   256
#define MAT  (MM*MM)
#define NMAT (BB*CHN)

typedef __nv_bfloat16 bf16;

// ---------------- scratch (device globals; no allocs allowed) ----------------
__device__ __align__(256) bf16 g_feat_hi [NMAT * MAT];
__device__ __align__(256) bf16 g_feat_lo [NMAT * MAT];
__device__ __align__(256) bf16 g_featT_hi[NMAT * MAT];
__device__ __align__(256) bf16 g_featT_lo[NMAT * MAT];
__device__ __align__(256) bf16 g_B2_hi   [NMAT * MAT];
__device__ __align__(256) bf16 g_B2_lo   [NMAT * MAT];
__device__ __align__(256) bf16 g_B2T_hi  [NMAT * MAT];
__device__ __align__(256) bf16 g_B2T_lo  [NMAT * MAT];
__device__ float g_part[NMAT * 4 * 4];   // [bc][tile 2x2][k: tr2,tr3,tr4,tr5]

// ---------------------------- helpers ---------------------------------------
__device__ __forceinline__ uint32_t smem_u32(const void* p) {
    uint32_t a;
    asm("{ .reg .u64 t; cvta.to.shared.u64 t, %1; cvt.u32.u64 %0, t; }" : "=r"(a) : "l"(p));
    return a;
}
#define CP16(dst, src) asm volatile("cp.async.cg.shared.global [%0], [%1], 16;" :: "r"((uint32_t)(dst)), "l"(src))
#define CP_COMMIT()    asm volatile("cp.async.commit_group;" ::: "memory")
#define CP_WAIT(n)     asm volatile("cp.async.wait_group %0;" :: "n"(n) : "memory")

#define MMA_BF16(d, a, b) \
    asm volatile("mma.sync.aligned.m16n8k16.row.col.f32.bf16.bf16.f32 " \
        "{%0,%1,%2,%3},{%4,%5,%6,%7},{%8,%9},{%0,%1,%2,%3};" \
        : "+f"((d)[0]), "+f"((d)[1]), "+f"((d)[2]), "+f"((d)[3]) \
        : "r"((a)[0]), "r"((a)[1]), "r"((a)[2]), "r"((a)[3]), "r"((b)[0]), "r"((b)[1]))

__device__ __forceinline__ void split_bf16(float v, bf16& h, bf16& l) {
    h = __float2bfloat16(v);
    l = __float2bfloat16(v - __bfloat162float(h));
}

// ---------------------------------------------------------------------------
// Conv: x[b,261,261] * w[16,1,6,6] + bias -> feat hi/lo + featT hi/lo (bf16)
// ---------------------------------------------------------------------------
__global__ void __launch_bounds__(256) conv_kernel(const float* __restrict__ x,
                                                   const float* __restrict__ w,
                                                   const float* __restrict__ bias) {
    __shared__ float xs[37][38];
    __shared__ float ws[CHN * 36];
    __shared__ float bs[CHN];
    __shared__ float tile[32][33];
    const int b  = blockIdx.z;
    const int bx = blockIdx.x * 32, by = blockIdx.y * 32;
    const int tx = threadIdx.x, ty = threadIdx.y;
    const int tid = ty * 32 + tx;

    for (int i = tid; i < 37 * 37; i += 256) {
        int r = i / 37, c = i % 37;
        xs[r][c] = x[b * NN * NN + (by + r) * NN + (bx + c)];
    }
    for (int i = tid; i < CHN * 36; i += 256) ws[i] = w[i];
    if (tid < CHN) bs[tid] = bias[tid];
    __syncthreads();

    float acc[4][CHN];
#pragma unroll
    for (int r = 0; r < 4; r++)
#pragma unroll
        for (int c = 0; c < CHN; c++) acc[r][c] = bs[c];

#pragma unroll
    for (int p = 0; p < 6; p++) {
#pragma unroll
        for (int q = 0; q < 6; q++) {
            float xv[4];
#pragma unroll
            for (int r = 0; r < 4; r++) xv[r] = xs[ty + 8 * r + p][tx + q];
#pragma unroll
            for (int c = 0; c < CHN; c++) {
                float wv = ws[c * 36 + p * 6 + q];
#pragma unroll
                for (int r = 0; r < 4; r++) acc[r][c] += xv[r] * wv;
            }
        }
    }

    // row-major hi/lo
#pragma unroll
    for (int c = 0; c < CHN; c++) {
        size_t base = (size_t)(b * CHN + c) * MAT;
#pragma unroll
        for (int r = 0; r < 4; r++) {
            int row = by + ty + 8 * r, col = bx + tx;
            bf16 h, l; split_bf16(acc[r][c], h, l);
            g_feat_hi[base + row * MM + col] = h;
            g_feat_lo[base + row * MM + col] = l;
        }
    }
    // transposed hi/lo via smem staging
    for (int c = 0; c < CHN; c++) {
        __syncthreads();
#pragma unroll
        for (int r = 0; r < 4; r++) tile[ty + 8 * r][tx] = acc[r][c];
        __syncthreads();
        size_t base = (size_t)(b * CHN + c) * MAT;
#pragma unroll
        for (int rr = 0; rr < 4; rr++) {
            int j = ty + 8 * rr;                        // local col -> featT row bx+j
            bf16 h, l; split_bf16(tile[tx][j], h, l);   // value at (by+tx, bx+j)
            size_t idx = base + (size_t)(bx + j) * MM + (by + tx);
            g_featT_hi[idx] = h;
            g_featT_lo[idx] = l;
        }
    }
}

// ---------------------------------------------------------------------------
// bf16 mma.sync GEMM, 128x128 tile, BK=32, double-buffered cp.async.
// C = feat(rows) @ B where Bt rows come from featT (IS2=0) or B2T (IS2=1).
// 3-term split: D = Ah*Bh + Ah*Bl + Al*Bh, fp32 accumulate.
// ---------------------------------------------------------------------------
#define PADK    40            // 32 + 8 pad, conflict-free
#define A_BYTES (128 * PADK * 2)      // 10240
#define OFF_AH  0
#define OFF_AL  10240
#define OFF_BH  20480
#define OFF_BL  30720
#define STAGE_B 40960
#define GEMM_SMEM 81920
#define CS_PAD  129

__device__ __forceinline__ void load_stage(uint32_t st,
        const bf16* __restrict__ Ah, const bf16* __restrict__ Al,
        const bf16* __restrict__ Bh, const bf16* __restrict__ Bl,
        int kb, int tid) {
#pragma unroll
    for (int it = 0; it < 2; ++it) {
        int u = it * 256 + tid;          // 0..511 chunk id
        int row = u >> 2, seg = u & 3;
        uint32_t doff = (uint32_t)(row * (PADK * 2) + seg * 16);
        const bf16* sa = Ah + row * MM + kb * 32 + seg * 8;
        const bf16* sl = Al + row * MM + kb * 32 + seg * 8;
        const bf16* sb = Bh + row * MM + kb * 32 + seg * 8;
        const bf16* sc = Bl + row * MM + kb * 32 + seg * 8;
        CP16(st + OFF_AH + doff, sa);
        CP16(st + OFF_AL + doff, sl);
        CP16(st + OFF_BH + doff, sb);
        CP16(st + OFF_BL + doff, sc);
    }
}

template <bool IS2>
__global__ void __launch_bounds__(256) gemm_kernel() {
    extern __shared__ char sm[];
    const uint32_t sbase = smem_u32(sm);
    const int tid  = threadIdx.x;
    const int lane = tid & 31;
    const int w    = tid >> 5;
    const int wm   = w >> 2;            // 0..1 -> 64-row slab
    const int wn   = w & 3;             // 0..3 -> 32-col slab
    const int bc   = blockIdx.z;
    const int row0 = blockIdx.y * 128;
    const int col0 = blockIdx.x * 128;
    const bool diag = (blockIdx.x == blockIdx.y);
    const size_t mbase = (size_t)bc * MAT;

    const bf16* Ah = g_feat_hi + mbase + (size_t)row0 * MM;
    const bf16* Al = g_feat_lo + mbase + (size_t)row0 * MM;
    const bf16* Bh = (IS2 ? g_B2T_hi : g_featT_hi) + mbase + (size_t)col0 * MM;
    const bf16* Bl = (IS2 ? g_B2T_lo : g_featT_lo) + mbase + (size_t)col0 * MM;

    float acc[4][4][4];
#pragma unroll
    for (int mi = 0; mi < 4; mi++)
#pragma unroll
        for (int ni = 0; ni < 4; ni++)
#pragma unroll
            for (int e = 0; e < 4; e++) acc[mi][ni][e] = 0.f;

    load_stage(sbase, Ah, Al, Bh, Bl, 0, tid);
    CP_COMMIT();

    for (int kb = 0; kb < 8; ++kb) {
        if (kb < 7) {
            load_stage(sbase + ((kb + 1) & 1) * STAGE_B, Ah, Al, Bh, Bl, kb + 1, tid);
            CP_COMMIT();
            CP_WAIT(1);
        } else {
            CP_WAIT(0);
        }
        __syncthreads();

        const char* st = sm + (kb & 1) * STAGE_B;
        const bf16* AHs = (const bf16*)(st + OFF_AH);
        const bf16* ALs = (const bf16*)(st + OFF_AL);
        const bf16* BHs = (const bf16*)(st + OFF_BH);
        const bf16* BLs = (const bf16*)(st + OFF_BL);

#pragma unroll
        for (int ks = 0; ks < 2; ++ks) {
            const int kcol = ks * 16 + (lane & 3) * 2;
            uint32_t ah[4][4], al[4][4], bh[4][2], bl[4][2];
#pragma unroll
            for (int mi = 0; mi < 4; mi++) {
                int r = wm * 64 + mi * 16 + (lane >> 2);
                ah[mi][0] = *(const uint32_t*)(AHs + r * PADK + kcol);
                ah[mi][1] = *(const uint32_t*)(AHs + (r + 8) * PADK + kcol);
                ah[mi][2] = *(const uint32_t*)(AHs + r * PADK + kcol + 8);
                ah[mi][3] = *(const uint32_t*)(AHs + (r + 8) * PADK + kcol + 8);
                al[mi][0] = *(const uint32_t*)(ALs + r * PADK + kcol);
                al[mi][1] = *(const uint32_t*)(ALs + (r + 8) * PADK + kcol);
                al[mi][2] = *(const uint32_t*)(ALs + r * PADK + kcol + 8);
                al[mi][3] = *(const uint32_t*)(ALs + (r + 8) * PADK + kcol + 8);
            }
#pragma unroll
            for (int ni = 0; ni < 4; ni++) {
                int n = wn * 32 + ni * 8 + (lane >> 2);
                bh[ni][0] = *(const uint32_t*)(BHs + n * PADK + kcol);
                bh[ni][1] = *(const uint32_t*)(BHs + n * PADK + kcol + 8);
                bl[ni][0] = *(const uint32_t*)(BLs + n * PADK + kcol);
                bl[ni][1] = *(const uint32_t*)(BLs + n * PADK + kcol + 8);
            }
#pragma unroll
            for (int mi = 0; mi < 4; mi++)
#pragma unroll
                for (int ni = 0; ni < 4; ni++) {
                    MMA_BF16(acc[mi][ni], ah[mi], bh[ni]);
                    MMA_BF16(acc[mi][ni], ah[mi], bl[ni]);
                    MMA_BF16(acc[mi][ni], al[mi], bh[ni]);
                }
        }
        __syncthreads();
    }

    // ---------------- epilogue: stage C through smem ----------------
    float* Cs = (float*)sm;                       // [128][129]
    float* red = (float*)(sm + 66560);
#pragma unroll
    for (int mi = 0; mi < 4; mi++)
#pragma unroll
        for (int ni = 0; ni < 4; ni++) {
            int r = wm * 64 + mi * 16 + (lane >> 2);
            int c = wn * 32 + ni * 8 + (lane & 3) * 2;
            Cs[r * CS_PAD + c]           = acc[mi][ni][0];
            Cs[r * CS_PAD + c + 1]       = acc[mi][ni][1];
            Cs[(r + 8) * CS_PAD + c]     = acc[mi][ni][2];
            Cs[(r + 8) * CS_PAD + c + 1] = acc[mi][ni][3];
        }
    __syncthreads();

    float p1 = 0.f, p2 = 0.f, p3 = 0.f;   // tr3, tr4, tr5 partials (IS2)
    float p0 = 0.f;                        // tr2 partial (!IS2)

    if (!IS2) {
        // write B2 (row-major) and B2T, bf16 hi/lo pairs
        for (int u = tid; u < 8192; u += 256) {
            int i = u >> 6, j2 = (u & 63) * 2;
            float v0 = Cs[i * CS_PAD + j2], v1 = Cs[i * CS_PAD + j2 + 1];
            bf16 h0, l0, h1, l1;
            split_bf16(v0, h0, l0); split_bf16(v1, h1, l1);
            size_t o = mbase + (size_t)(row0 + i) * MM + col0 + j2;
            *(__nv_bfloat162*)&g_B2_hi[o] = __nv_bfloat162(h0, h1);
            *(__nv_bfloat162*)&g_B2_lo[o] = __nv_bfloat162(l0, l1);
        }
        for (int u = tid; u < 8192; u += 256) {
            int cL = u >> 6, r2 = (u & 63) * 2;
            float v0 = Cs[r2 * CS_PAD + cL], v1 = Cs[(r2 + 1) * CS_PAD + cL];
            bf16 h0, l0, h1, l1;
            split_bf16(v0, h0, l0); split_bf16(v1, h1, l1);
            size_t o = mbase + (size_t)(col0 + cL) * MM + row0 + r2;
            *(__nv_bfloat162*)&g_B2T_hi[o] = __nv_bfloat162(h0, h1);
            *(__nv_bfloat162*)&g_B2T_lo[o] = __nv_bfloat162(l0, l1);
        }
        if (diag && tid < 128) p0 = Cs[tid * CS_PAD + tid];
    } else {
        for (int u = tid; u < 8192; u += 256) {
            int i = u >> 6, j2 = (u & 63) * 2;
            float b30 = Cs[i * CS_PAD + j2], b31 = Cs[i * CS_PAD + j2 + 1];
            size_t o = mbase + (size_t)(row0 + i) * MM + col0 + j2;
            __nv_bfloat162 th = *(const __nv_bfloat162*)&g_B2T_hi[o];
            __nv_bfloat162 tl = *(const __nv_bfloat162*)&g_B2T_lo[o];
            __nv_bfloat162 bh2 = *(const __nv_bfloat162*)&g_B2_hi[o];
            __nv_bfloat162 bl2 = *(const __nv_bfloat162*)&g_B2_lo[o];
            float t0 = __bfloat162float(th.x) + __bfloat162float(tl.x);
            float t1 = __bfloat162float(th.y) + __bfloat162float(tl.y);
            float b0 = __bfloat162float(bh2.x) + __bfloat162float(bl2.x);
            float b1 = __bfloat162float(bh2.y) + __bfloat162float(bl2.y);
            p3 += b30 * t0 + b31 * t1;        // tr(A^5)
            p2 += b0 * t0 + b1 * t1;          // tr(A^4)
            if (diag) {
                if (i == j2)     p1 += b30;   // tr(A^3)
                if (i == j2 + 1) p1 += b31;
            }
        }
    }

    // deterministic block reduce
#pragma unroll
    for (int off = 16; off; off >>= 1) {
        p0 += __shfl_down_sync(0xFFFFFFFFu, p0, off);
        p1 += __shfl_down_sync(0xFFFFFFFFu, p1, off);
        p2 += __shfl_down_sync(0xFFFFFFFFu, p2, off);
        p3 += __shfl_down_sync(0xFFFFFFFFu, p3, off);
    }
    __syncthreads();
    if (lane == 0) {
        red[w * 4 + 0] = p0; red[w * 4 + 1] = p1;
        red[w * 4 + 2] = p2; red[w * 4 + 3] = p3;
    }
    __syncthreads();
    if (tid == 0) {
        float s0 = 0.f, s1 = 0.f, s2 = 0.f, s3 = 0.f;
        for (int q = 0; q < 8; q++) {
            s0 += red[q * 4]; s1 += red[q * 4 + 1];
            s2 += red[q * 4 + 2]; s3 += red[q * 4 + 3];
        }
        int slot = (bc * 4 + (int)(blockIdx.y * 2 + blockIdx.x)) * 4;
        if (!IS2) g_part[slot + 0] = s0;
        else { g_part[slot + 1] = s1; g_part[slot + 2] = s2; g_part[slot + 3] = s3; }
    }
}

// ---------------------------------------------------------------------------
// Combine: out[b] = sum coef[c,i,j] * tr_{i+2}^(j+1) / 65536^(i+j+1)
// ---------------------------------------------------------------------------
__global__ void __launch_bounds__(512) final_kernel(const float* __restrict__ coef,
                                                    float* __restrict__ out) {
    int t = threadIdx.x;
    int b = t >> 4, c = t & 15;
    int bc = b * CHN + c;
    double tr[4];
#pragma unroll
    for (int k = 0; k < 4; k++) {
        float s = 0.f;
#pragma unroll
        for (int tile = 0; tile < 4; tile++) s += g_part[(bc * 4 + tile) * 4 + k];
        tr[k] = (double)s;
    }
    double sum = 0.0;
#pragma unroll
    for (int i = 0; i < 4; i++) {
        double p = tr[i];
        double tp = p;
#pragma unroll
        for (int j = 0; j < 4; j++) {
            double v = ldexp(tp, -16 * (i + j + 1));
            sum += (double)coef[c * 16 + i * 4 + j] * v;
            tp *= p;
        }
    }
#pragma unroll
    for (int off = 8; off; off >>= 1)
        sum += __shfl_down_sync(0xFFFFFFFFu, sum, off, 16);
    if (c == 0) out[b] = (float)sum;
}

extern "C" void kernel_launch(void* const* d_in, const int* in_sizes, int n_in,
                              void* d_out, int out_size) {
    const float* x    = (const float*)d_in[0];
    const float* w    = (const float*)d_in[1];
    const float* bias = (const float*)d_in[2];
    const float* coef = (const float*)d_in[3];
    float* out = (float*)d_out;

    cudaFuncSetAttribute(gemm_kernel<false>, cudaFuncAttributeMaxDynamicSharedMemorySize, GEMM_SMEM);
    cudaFuncSetAttribute(gemm_kernel<true>,  cudaFuncAttributeMaxDynamicSharedMemorySize, GEMM_SMEM);

    conv_kernel<<<dim3(8, 8, BB), dim3(32, 8)>>>(x, w, bias);
    gemm_kernel<false><<<dim3(2, 2, NMAT), 256, GEMM_SMEM>>>();
    gemm_kernel<true> <<<dim3(2, 2, NMAT), 256, GEMM_SMEM>>>();
    final_kernel<<<1, 512>>>(coef, out);
}

// round 4
// speedup vs baseline: 2.4578x; 1.2576x over previous
#include <cuda_runtime.h>
#include <cuda_fp16.h>
#include <cstdint>

#define BB   32
#define CHN  16
#define NN   261
#define MM   256
#define MAT  (MM*MM)
#define NMAT (BB*CHN)

// ---------------- scratch (device globals; no allocs allowed) ----------------
__device__ __align__(256) __half g_Ah  [NMAT * MAT];   // feat fp16 hi (row-major)
__device__ __align__(256) __half g_Al  [NMAT * MAT];   // feat fp16 lo (row-major)
__device__ __align__(256) __half g_Bh  [NMAT * MAT];   // featT fp16 hi
__device__ __align__(256) __half g_B2h [NMAT * MAT];   // B2 row-major hi
__device__ __align__(256) __half g_B2l [NMAT * MAT];   // B2 row-major lo
__device__ __align__(256) __half g_B2Th[NMAT * MAT];   // B2T hi (stage2 operand + epi)
__device__ __align__(256) __half g_B2Tl[NMAT * MAT];   // B2T lo (epi precision)
__device__ float g_part[NMAT * 4 * 4];   // [bc][tile 2x2][k: tr2,tr3,tr4,tr5]

// ---------------------------- helpers ---------------------------------------
__device__ __forceinline__ uint32_t smem_u32(const void* p) {
    uint32_t a;
    asm("{ .reg .u64 t; cvta.to.shared.u64 t, %1; cvt.u32.u64 %0, t; }" : "=r"(a) : "l"(p));
    return a;
}
#define CP16(dst, src) asm volatile("cp.async.cg.shared.global [%0], [%1], 16;" :: "r"((uint32_t)(dst)), "l"(src))
#define CP_COMMIT()    asm volatile("cp.async.commit_group;" ::: "memory")
#define CP_WAIT(n)     asm volatile("cp.async.wait_group %0;" :: "n"(n) : "memory")

#define MMA_F16(d, a, b) \
    asm volatile("mma.sync.aligned.m16n8k16.row.col.f32.f16.f16.f32 " \
        "{%0,%1,%2,%3},{%4,%5,%6,%7},{%8,%9},{%0,%1,%2,%3};" \
        : "+f"((d)[0]), "+f"((d)[1]), "+f"((d)[2]), "+f"((d)[3]) \
        : "r"((a)[0]), "r"((a)[1]), "r"((a)[2]), "r"((a)[3]), "r"((b)[0]), "r"((b)[1]))

__device__ __forceinline__ void split_f16(float v, __half& h, __half& l) {
    h = __float2half_rn(v);
    l = __float2half_rn(v - __half2float(h));
}

// ---------------------------------------------------------------------------
// Conv: x[b,261,261] * w[16,1,6,6] + bias -> g_Ah/g_Al (row) + g_Bh (transposed)
// ---------------------------------------------------------------------------
__global__ void __launch_bounds__(256) conv_kernel(const float* __restrict__ x,
                                                   const float* __restrict__ w,
                                                   const float* __restrict__ bias) {
    __shared__ float xs[37][38];
    __shared__ float ws[CHN * 36];
    __shared__ float bs[CHN];
    __shared__ float tile4[4][32][33];
    const int b  = blockIdx.z;
    const int bx = blockIdx.x * 32, by = blockIdx.y * 32;
    const int tx = threadIdx.x, ty = threadIdx.y;
    const int tid = ty * 32 + tx;

    for (int i = tid; i < 37 * 37; i += 256) {
        int r = i / 37, c = i % 37;
        xs[r][c] = x[b * NN * NN + (by + r) * NN + (bx + c)];
    }
    for (int i = tid; i < CHN * 36; i += 256) ws[i] = w[i];
    if (tid < CHN) bs[tid] = bias[tid];
    __syncthreads();

    float acc[4][CHN];
#pragma unroll
    for (int r = 0; r < 4; r++)
#pragma unroll
        for (int c = 0; c < CHN; c++) acc[r][c] = bs[c];

#pragma unroll
    for (int p = 0; p < 6; p++) {
#pragma unroll
        for (int q = 0; q < 6; q++) {
            float xv[4];
#pragma unroll
            for (int r = 0; r < 4; r++) xv[r] = xs[ty + 8 * r + p][tx + q];
#pragma unroll
            for (int c = 0; c < CHN; c++) {
                float wv = ws[c * 36 + p * 6 + q];
#pragma unroll
                for (int r = 0; r < 4; r++) acc[r][c] += xv[r] * wv;
            }
        }
    }

    // row-major hi/lo pairs
#pragma unroll
    for (int c = 0; c < CHN; c++) {
        size_t base = (size_t)(b * CHN + c) * MAT;
#pragma unroll
        for (int r = 0; r < 4; r++) {
            int row = by + ty + 8 * r, col = bx + tx;
            __half h, l; split_f16(acc[r][c], h, l);
            g_Ah[base + row * MM + col] = h;
            g_Al[base + row * MM + col] = l;
        }
    }
    // transposed hi (4 channels per smem pass)
    for (int g = 0; g < 4; g++) {
        __syncthreads();
#pragma unroll
        for (int cc = 0; cc < 4; cc++)
#pragma unroll
            for (int r = 0; r < 4; r++) tile4[cc][ty + 8 * r][tx] = acc[r][g * 4 + cc];
        __syncthreads();
#pragma unroll
        for (int cc = 0; cc < 4; cc++) {
            size_t base = (size_t)(b * CHN + g * 4 + cc) * MAT;
#pragma unroll
            for (int rr = 0; rr < 4; rr++) {
                int j = ty + 8 * rr;                       // value at (by+tx, bx+j)
                float v = tile4[cc][tx][j];
                g_Bh[base + (size_t)(bx + j) * MM + (by + tx)] = __float2half_rn(v);
            }
        }
    }
}

// ---------------------------------------------------------------------------
// fp16 mma.sync GEMM, 128x128 tile, BK=32, 3-stage cp.async ring.
// C = A @ B with 2-term split: D = Ah*Bh + Al*Bh (fp32 acc).
// IS2=0: B = feat^T (g_Bh)  -> writes B2/B2T f16 pairs + tr2 partial
// IS2=1: B = B2^T  (g_B2Th) -> tr3/tr4/tr5 partials; B3 never stored
// ---------------------------------------------------------------------------
#define PADK    40                     // halves per row (32 + 8 pad)
#define OFF_AH  0
#define OFF_AL  10240
#define OFF_BH  20480
#define STAGE_B 30720
#define GEMM_SMEM (3 * STAGE_B)        // 92160
#define CS_PAD  129

__device__ __forceinline__ void load_stage(uint32_t st,
        const __half* __restrict__ Ah, const __half* __restrict__ Al,
        const __half* __restrict__ Bh, int kb, int tid) {
#pragma unroll
    for (int it = 0; it < 2; ++it) {
        int u = it * 256 + tid;          // 0..511
        int row = u >> 2, seg = u & 3;
        uint32_t doff = (uint32_t)(row * (PADK * 2) + seg * 16);
        CP16(st + OFF_AH + doff, Ah + row * MM + kb * 32 + seg * 8);
        CP16(st + OFF_AL + doff, Al + row * MM + kb * 32 + seg * 8);
        CP16(st + OFF_BH + doff, Bh + row * MM + kb * 32 + seg * 8);
    }
}

template <bool IS2>
__global__ void __launch_bounds__(256) gemm_kernel() {
    extern __shared__ char sm[];
    const uint32_t sbase = smem_u32(sm);
    const int tid  = threadIdx.x;
    const int lane = tid & 31;
    const int w    = tid >> 5;
    const int wm   = w >> 2;            // 0..1 -> 64-row slab
    const int wn   = w & 3;             // 0..3 -> 32-col slab
    const int bc   = blockIdx.z;
    const int row0 = blockIdx.y * 128;
    const int col0 = blockIdx.x * 128;
    const bool diag = (blockIdx.x == blockIdx.y);
    const size_t mbase = (size_t)bc * MAT;

    const __half* Ah = g_Ah + mbase + (size_t)row0 * MM;
    const __half* Al = g_Al + mbase + (size_t)row0 * MM;
    const __half* Bh = (IS2 ? g_B2Th : g_Bh) + mbase + (size_t)col0 * MM;

    float acc[4][4][4];
#pragma unroll
    for (int mi = 0; mi < 4; mi++)
#pragma unroll
        for (int ni = 0; ni < 4; ni++)
#pragma unroll
            for (int e = 0; e < 4; e++) acc[mi][ni][e] = 0.f;

    load_stage(sbase + 0 * STAGE_B, Ah, Al, Bh, 0, tid);
    CP_COMMIT();
    load_stage(sbase + 1 * STAGE_B, Ah, Al, Bh, 1, tid);
    CP_COMMIT();

    for (int kb = 0; kb < 8; ++kb) {
        if (kb < 7) { CP_WAIT(1); } else { CP_WAIT(0); }
        __syncthreads();
        if (kb + 2 < 8) {
            int s = (kb + 2) % 3;
            load_stage(sbase + s * STAGE_B, Ah, Al, Bh, kb + 2, tid);
            CP_COMMIT();
        }

        const char* st = sm + (kb % 3) * STAGE_B;
        const __half* AHs = (const __half*)(st + OFF_AH);
        const __half* ALs = (const __half*)(st + OFF_AL);
        const __half* BHs = (const __half*)(st + OFF_BH);

#pragma unroll
        for (int ks = 0; ks < 2; ++ks) {
            const int kcol = ks * 16 + (lane & 3) * 2;
            uint32_t ah[4][4], al[4][4], bh[4][2];
#pragma unroll
            for (int mi = 0; mi < 4; mi++) {
                int r = wm * 64 + mi * 16 + (lane >> 2);
                ah[mi][0] = *(const uint32_t*)(AHs + r * PADK + kcol);
                ah[mi][1] = *(const uint32_t*)(AHs + (r + 8) * PADK + kcol);
                ah[mi][2] = *(const uint32_t*)(AHs + r * PADK + kcol + 8);
                ah[mi][3] = *(const uint32_t*)(AHs + (r + 8) * PADK + kcol + 8);
                al[mi][0] = *(const uint32_t*)(ALs + r * PADK + kcol);
                al[mi][1] = *(const uint32_t*)(ALs + (r + 8) * PADK + kcol);
                al[mi][2] = *(const uint32_t*)(ALs + r * PADK + kcol + 8);
                al[mi][3] = *(const uint32_t*)(ALs + (r + 8) * PADK + kcol + 8);
            }
#pragma unroll
            for (int ni = 0; ni < 4; ni++) {
                int n = wn * 32 + ni * 8 + (lane >> 2);
                bh[ni][0] = *(const uint32_t*)(BHs + n * PADK + kcol);
                bh[ni][1] = *(const uint32_t*)(BHs + n * PADK + kcol + 8);
            }
#pragma unroll
            for (int mi = 0; mi < 4; mi++)
#pragma unroll
                for (int ni = 0; ni < 4; ni++) {
                    MMA_F16(acc[mi][ni], ah[mi], bh[ni]);
                    MMA_F16(acc[mi][ni], al[mi], bh[ni]);
                }
        }
    }
    __syncthreads();

    // ---------------- epilogue: stage C through smem ----------------
    float* Cs  = (float*)sm;                      // [128][129]
    float* red = (float*)(sm + 66560);
#pragma unroll
    for (int mi = 0; mi < 4; mi++)
#pragma unroll
        for (int ni = 0; ni < 4; ni++) {
            int r = wm * 64 + mi * 16 + (lane >> 2);
            int c = wn * 32 + ni * 8 + (lane & 3) * 2;
            Cs[r * CS_PAD + c]           = acc[mi][ni][0];
            Cs[r * CS_PAD + c + 1]       = acc[mi][ni][1];
            Cs[(r + 8) * CS_PAD + c]     = acc[mi][ni][2];
            Cs[(r + 8) * CS_PAD + c + 1] = acc[mi][ni][3];
        }
    __syncthreads();

    float p0 = 0.f;                    // tr2 (!IS2)
    float p1 = 0.f, p2 = 0.f, p3 = 0.f; // tr3, tr4, tr5 (IS2)

    if (!IS2) {
        for (int u = tid; u < 8192; u += 256) {
            int i = u >> 6, j2 = (u & 63) * 2;
            float v0 = Cs[i * CS_PAD + j2], v1 = Cs[i * CS_PAD + j2 + 1];
            __half h0, l0, h1, l1;
            split_f16(v0, h0, l0); split_f16(v1, h1, l1);
            size_t o = mbase + (size_t)(row0 + i) * MM + col0 + j2;
            *(__half2*)&g_B2h[o] = __halves2half2(h0, h1);
            *(__half2*)&g_B2l[o] = __halves2half2(l0, l1);
        }
        for (int u = tid; u < 8192; u += 256) {
            int cL = u >> 6, r2 = (u & 63) * 2;
            float v0 = Cs[r2 * CS_PAD + cL], v1 = Cs[(r2 + 1) * CS_PAD + cL];
            __half h0, l0, h1, l1;
            split_f16(v0, h0, l0); split_f16(v1, h1, l1);
            size_t o = mbase + (size_t)(col0 + cL) * MM + row0 + r2;
            *(__half2*)&g_B2Th[o] = __halves2half2(h0, h1);
            *(__half2*)&g_B2Tl[o] = __halves2half2(l0, l1);
        }
        if (diag && tid < 128) p0 = Cs[tid * CS_PAD + tid];
    } else {
        for (int u = tid; u < 8192; u += 256) {
            int i = u >> 6, j2 = (u & 63) * 2;
            float b30 = Cs[i * CS_PAD + j2], b31 = Cs[i * CS_PAD + j2 + 1];
            size_t o = mbase + (size_t)(row0 + i) * MM + col0 + j2;
            float2 th = __half22float2(*(const __half2*)&g_B2Th[o]);
            float2 tl = __half22float2(*(const __half2*)&g_B2Tl[o]);
            float2 bh2 = __half22float2(*(const __half2*)&g_B2h[o]);
            float2 bl2 = __half22float2(*(const __half2*)&g_B2l[o]);
            float t0 = th.x + tl.x, t1 = th.y + tl.y;      // B2[j,i]
            float b0 = bh2.x + bl2.x, b1 = bh2.y + bl2.y;  // B2[i,j]
            p3 += b30 * t0 + b31 * t1;        // tr(A^5)
            p2 += b0 * t0 + b1 * t1;          // tr(A^4)
            if (diag) {
                if (i == j2)     p1 += b30;   // tr(A^3)
                if (i == j2 + 1) p1 += b31;
            }
        }
    }

    // deterministic block reduce
#pragma unroll
    for (int off = 16; off; off >>= 1) {
        p0 += __shfl_down_sync(0xFFFFFFFFu, p0, off);
        p1 += __shfl_down_sync(0xFFFFFFFFu, p1, off);
        p2 += __shfl_down_sync(0xFFFFFFFFu, p2, off);
        p3 += __shfl_down_sync(0xFFFFFFFFu, p3, off);
    }
    __syncthreads();
    if (lane == 0) {
        red[w * 4 + 0] = p0; red[w * 4 + 1] = p1;
        red[w * 4 + 2] = p2; red[w * 4 + 3] = p3;
    }
    __syncthreads();
    if (tid == 0) {
        float s0 = 0.f, s1 = 0.f, s2 = 0.f, s3 = 0.f;
        for (int q = 0; q < 8; q++) {
            s0 += red[q * 4]; s1 += red[q * 4 + 1];
            s2 += red[q * 4 + 2]; s3 += red[q * 4 + 3];
        }
        int slot = (bc * 4 + (int)(blockIdx.y * 2 + blockIdx.x)) * 4;
        if (!IS2) g_part[slot + 0] = s0;
        else { g_part[slot + 1] = s1; g_part[slot + 2] = s2; g_part[slot + 3] = s3; }
    }
}

// ---------------------------------------------------------------------------
// Combine: out[b] = sum coef[c,i,j] * tr_{i+2}^(j+1) / 65536^(i+j+1)
// ---------------------------------------------------------------------------
__global__ void __launch_bounds__(512) final_kernel(const float* __restrict__ coef,
                                                    float* __restrict__ out) {
    int t = threadIdx.x;
    int b = t >> 4, c = t & 15;
    int bc = b * CHN + c;
    double tr[4];
#pragma unroll
    for (int k = 0; k < 4; k++) {
        float s = 0.f;
#pragma unroll
        for (int tile = 0; tile < 4; tile++) s += g_part[(bc * 4 + tile) * 4 + k];
        tr[k] = (double)s;
    }
    double sum = 0.0;
#pragma unroll
    for (int i = 0; i < 4; i++) {
        double p = tr[i];
        double tp = p;
#pragma unroll
        for (int j = 0; j < 4; j++) {
            double v = ldexp(tp, -16 * (i + j + 1));
            sum += (double)coef[c * 16 + i * 4 + j] * v;
            tp *= p;
        }
    }
#pragma unroll
    for (int off = 8; off; off >>= 1)
        sum += __shfl_down_sync(0xFFFFFFFFu, sum, off, 16);
    if (c == 0) out[b] = (float)sum;
}

extern "C" void kernel_launch(void* const* d_in, const int* in_sizes, int n_in,
                              void* d_out, int out_size) {
    const float* x    = (const float*)d_in[0];
    const float* w    = (const float*)d_in[1];
    const float* bias = (const float*)d_in[2];
    const float* coef = (const float*)d_in[3];
    float* out = (float*)d_out;

    cudaFuncSetAttribute(gemm_kernel<false>, cudaFuncAttributeMaxDynamicSharedMemorySize, GEMM_SMEM);
    cudaFuncSetAttribute(gemm_kernel<true>,  cudaFuncAttributeMaxDynamicSharedMemorySize, GEMM_SMEM);

    conv_kernel<<<dim3(8, 8, BB), dim3(32, 8)>>>(x, w, bias);
    gemm_kernel<false><<<dim3(2, 2, NMAT), 256, GEMM_SMEM>>>();
    gemm_kernel<true> <<<dim3(2, 2, NMAT), 256, GEMM_SMEM>>>();
    final_kernel<<<1, 512>>>(coef, out);
}

// round 5
// speedup vs baseline: 2.6015x; 1.0585x over previous
#include <cuda_runtime.h>
#include <cuda_fp16.h>
#include <cstdint>

#define BB   32
#define CHN  16
#define NN   261
#define MM   256
#define MAT  (MM*MM)
#define NMAT (BB*CHN)

// ---------------- scratch (device globals; no allocs allowed) ----------------
__device__ __align__(256) __half g_Ah  [NMAT * MAT];   // feat fp16 hi (row-major)
__device__ __align__(256) __half g_Al  [NMAT * MAT];   // feat fp16 lo (row-major)
__device__ __align__(256) __half g_Bh  [NMAT * MAT];   // featT fp16 hi
__device__ __align__(256) __half g_B2h [NMAT * MAT];   // B2 row-major hi
__device__ __align__(256) __half g_B2l [NMAT * MAT];   // B2 row-major lo
__device__ __align__(256) __half g_B2Th[NMAT * MAT];   // B2T hi (stage2 operand + epi)
__device__ float g_part[NMAT * 4 * 4];   // [bc][tile 2x2][k: tr2,tr3,tr4,tr5]

// ---------------------------- helpers ---------------------------------------
__device__ __forceinline__ uint32_t smem_u32(const void* p) {
    uint32_t a;
    asm("{ .reg .u64 t; cvta.to.shared.u64 t, %1; cvt.u32.u64 %0, t; }" : "=r"(a) : "l"(p));
    return a;
}
#define CP16(dst, src) asm volatile("cp.async.cg.shared.global [%0], [%1], 16;" :: "r"((uint32_t)(dst)), "l"(src))
#define CP_COMMIT()    asm volatile("cp.async.commit_group;" ::: "memory")
#define CP_WAIT(n)     asm volatile("cp.async.wait_group %0;" :: "n"(n) : "memory")

#define MMA_F16(d, a, b) \
    asm volatile("mma.sync.aligned.m16n8k16.row.col.f32.f16.f16.f32 " \
        "{%0,%1,%2,%3},{%4,%5,%6,%7},{%8,%9},{%0,%1,%2,%3};" \
        : "+f"((d)[0]), "+f"((d)[1]), "+f"((d)[2]), "+f"((d)[3]) \
        : "r"((a)[0]), "r"((a)[1]), "r"((a)[2]), "r"((a)[3]), "r"((b)[0]), "r"((b)[1]))

#define LDSM4(r, addr) \
    asm volatile("ldmatrix.sync.aligned.m8n8.x4.shared.b16 {%0,%1,%2,%3}, [%4];" \
        : "=r"((r)[0]), "=r"((r)[1]), "=r"((r)[2]), "=r"((r)[3]) : "r"(addr))

__device__ __forceinline__ void split_f16(float v, __half& h, __half& l) {
    h = __float2half_rn(v);
    l = __float2half_rn(v - __half2float(h));
}

// ---------------------------------------------------------------------------
// Conv: x[b,261,261] * w[16,1,6,6] + bias -> g_Ah/g_Al (row) + g_Bh (transposed)
// ---------------------------------------------------------------------------
__global__ void __launch_bounds__(256) conv_kernel(const float* __restrict__ x,
                                                   const float* __restrict__ w,
                                                   const float* __restrict__ bias) {
    __shared__ float xs[37][38];
    __shared__ float ws[CHN * 36];
    __shared__ float bs[CHN];
    __shared__ float tile4[4][32][33];
    const int b  = blockIdx.z;
    const int bx = blockIdx.x * 32, by = blockIdx.y * 32;
    const int tx = threadIdx.x, ty = threadIdx.y;
    const int tid = ty * 32 + tx;

    for (int i = tid; i < 37 * 37; i += 256) {
        int r = i / 37, c = i % 37;
        xs[r][c] = x[b * NN * NN + (by + r) * NN + (bx + c)];
    }
    for (int i = tid; i < CHN * 36; i += 256) ws[i] = w[i];
    if (tid < CHN) bs[tid] = bias[tid];
    __syncthreads();

    float acc[4][CHN];
#pragma unroll
    for (int r = 0; r < 4; r++)
#pragma unroll
        for (int c = 0; c < CHN; c++) acc[r][c] = bs[c];

#pragma unroll
    for (int p = 0; p < 6; p++) {
#pragma unroll
        for (int q = 0; q < 6; q++) {
            float xv[4];
#pragma unroll
            for (int r = 0; r < 4; r++) xv[r] = xs[ty + 8 * r + p][tx + q];
#pragma unroll
            for (int c = 0; c < CHN; c++) {
                float wv = ws[c * 36 + p * 6 + q];
#pragma unroll
                for (int r = 0; r < 4; r++) acc[r][c] += xv[r] * wv;
            }
        }
    }

    // row-major hi/lo pairs
#pragma unroll
    for (int c = 0; c < CHN; c++) {
        size_t base = (size_t)(b * CHN + c) * MAT;
#pragma unroll
        for (int r = 0; r < 4; r++) {
            int row = by + ty + 8 * r, col = bx + tx;
            __half h, l; split_f16(acc[r][c], h, l);
            g_Ah[base + row * MM + col] = h;
            g_Al[base + row * MM + col] = l;
        }
    }
    // transposed hi (4 channels per smem pass)
    for (int g = 0; g < 4; g++) {
        __syncthreads();
#pragma unroll
        for (int cc = 0; cc < 4; cc++)
#pragma unroll
            for (int r = 0; r < 4; r++) tile4[cc][ty + 8 * r][tx] = acc[r][g * 4 + cc];
        __syncthreads();
#pragma unroll
        for (int cc = 0; cc < 4; cc++) {
            size_t base = (size_t)(b * CHN + g * 4 + cc) * MAT;
#pragma unroll
            for (int rr = 0; rr < 4; rr++) {
                int j = ty + 8 * rr;                       // value at (by+tx, bx+j)
                float v = tile4[cc][tx][j];
                g_Bh[base + (size_t)(bx + j) * MM + (by + tx)] = __float2half_rn(v);
            }
        }
    }
}

// ---------------------------------------------------------------------------
// fp16 mma.sync GEMM, 128x128 tile, BK=32, 3-stage cp.async ring, ldmatrix.
// C = A @ B with 2-term split: D = Ah*Bh + Al*Bh (fp32 acc).
// IS2=0: B = feat^T (g_Bh)  -> writes B2/B2T f16 + tr2 partial
// IS2=1: B = B2^T  (g_B2Th) -> tr3/tr4/tr5 partials; B3 never stored
// ---------------------------------------------------------------------------
#define PADK    40                     // halves per row (32 + 8 pad); 80B stride
#define OFF_AH  0
#define OFF_AL  10240
#define OFF_BH  20480
#define STAGE_B 30720
#define GEMM_SMEM (3 * STAGE_B)        // 92160
#define CS_PAD  129

__device__ __forceinline__ void load_stage(uint32_t st,
        const __half* __restrict__ Ah, const __half* __restrict__ Al,
        const __half* __restrict__ Bh, int kb, int tid) {
#pragma unroll
    for (int it = 0; it < 2; ++it) {
        int u = it * 256 + tid;          // 0..511
        int row = u >> 2, seg = u & 3;
        uint32_t doff = (uint32_t)(row * (PADK * 2) + seg * 16);
        CP16(st + OFF_AH + doff, Ah + row * MM + kb * 32 + seg * 8);
        CP16(st + OFF_AL + doff, Al + row * MM + kb * 32 + seg * 8);
        CP16(st + OFF_BH + doff, Bh + row * MM + kb * 32 + seg * 8);
    }
}

template <bool IS2>
__global__ void __launch_bounds__(256) gemm_kernel() {
    extern __shared__ char sm[];
    const uint32_t sbase = smem_u32(sm);
    const int tid  = threadIdx.x;
    const int lane = tid & 31;
    const int w    = tid >> 5;
    const int wm   = w >> 2;            // 0..1 -> 64-row slab
    const int wn   = w & 3;             // 0..3 -> 32-col slab
    const int bc   = blockIdx.z;
    const int row0 = blockIdx.y * 128;
    const int col0 = blockIdx.x * 128;
    const bool diag = (blockIdx.x == blockIdx.y);
    const size_t mbase = (size_t)bc * MAT;

    const __half* Ah = g_Ah + mbase + (size_t)row0 * MM;
    const __half* Al = g_Al + mbase + (size_t)row0 * MM;
    const __half* Bh = (IS2 ? g_B2Th : g_Bh) + mbase + (size_t)col0 * MM;

    // ldmatrix per-lane row offsets (bytes), conflict-free with 80B row stride
    const uint32_t aRowOff = (uint32_t)(((lane & 15) * PADK + ((lane >> 4) << 3)) * 2)
                           + (uint32_t)(wm * 64 * PADK * 2);
    const uint32_t bRowOff = (uint32_t)((((lane & 7) + ((lane >> 4) << 3)) * PADK
                           + (((lane >> 3) & 1) << 3)) * 2)
                           + (uint32_t)(wn * 32 * PADK * 2);

    float acc[4][4][4];
#pragma unroll
    for (int mi = 0; mi < 4; mi++)
#pragma unroll
        for (int ni = 0; ni < 4; ni++)
#pragma unroll
            for (int e = 0; e < 4; e++) acc[mi][ni][e] = 0.f;

    load_stage(sbase + 0 * STAGE_B, Ah, Al, Bh, 0, tid);
    CP_COMMIT();
    load_stage(sbase + 1 * STAGE_B, Ah, Al, Bh, 1, tid);
    CP_COMMIT();

    for (int kb = 0; kb < 8; ++kb) {
        if (kb < 7) { CP_WAIT(1); } else { CP_WAIT(0); }
        __syncthreads();
        if (kb + 2 < 8) {
            int s = (kb + 2) % 3;
            load_stage(sbase + s * STAGE_B, Ah, Al, Bh, kb + 2, tid);
            CP_COMMIT();
        }

        const uint32_t st = sbase + (uint32_t)((kb % 3) * STAGE_B);
        const uint32_t aH = st + OFF_AH + aRowOff;
        const uint32_t aL = st + OFF_AL + aRowOff;
        const uint32_t bB = st + OFF_BH + bRowOff;

#pragma unroll
        for (int ks = 0; ks < 2; ++ks) {
            const uint32_t ko = (uint32_t)(ks * 32);      // 16 halves
            uint32_t ah[4][4], al[4][4], bq[2][4];
#pragma unroll
            for (int mi = 0; mi < 4; mi++) LDSM4(ah[mi], aH + (uint32_t)(mi * 16 * PADK * 2) + ko);
#pragma unroll
            for (int mi = 0; mi < 4; mi++) LDSM4(al[mi], aL + (uint32_t)(mi * 16 * PADK * 2) + ko);
#pragma unroll
            for (int q = 0; q < 2; q++)    LDSM4(bq[q], bB + (uint32_t)(q * 16 * PADK * 2) + ko);
#pragma unroll
            for (int mi = 0; mi < 4; mi++)
#pragma unroll
                for (int ni = 0; ni < 4; ni++) {
                    MMA_F16(acc[mi][ni], ah[mi], &bq[ni >> 1][(ni & 1) * 2]);
                    MMA_F16(acc[mi][ni], al[mi], &bq[ni >> 1][(ni & 1) * 2]);
                }
        }
    }
    __syncthreads();

    // ---------------- epilogue: stage C through smem ----------------
    float* Cs  = (float*)sm;                      // [128][129]
    float* red = (float*)(sm + 66560);
#pragma unroll
    for (int mi = 0; mi < 4; mi++)
#pragma unroll
        for (int ni = 0; ni < 4; ni++) {
            int r = wm * 64 + mi * 16 + (lane >> 2);
            int c = wn * 32 + ni * 8 + (lane & 3) * 2;
            Cs[r * CS_PAD + c]           = acc[mi][ni][0];
            Cs[r * CS_PAD + c + 1]       = acc[mi][ni][1];
            Cs[(r + 8) * CS_PAD + c]     = acc[mi][ni][2];
            Cs[(r + 8) * CS_PAD + c + 1] = acc[mi][ni][3];
        }
    __syncthreads();

    float p0 = 0.f;                    // tr2 (!IS2)
    float p1 = 0.f, p2 = 0.f, p3 = 0.f; // tr3, tr4, tr5 (IS2)

    if (!IS2) {
        for (int u = tid; u < 8192; u += 256) {
            int i = u >> 6, j2 = (u & 63) * 2;
            float v0 = Cs[i * CS_PAD + j2], v1 = Cs[i * CS_PAD + j2 + 1];
            __half h0, l0, h1, l1;
            split_f16(v0, h0, l0); split_f16(v1, h1, l1);
            size_t o = mbase + (size_t)(row0 + i) * MM + col0 + j2;
            *(__half2*)&g_B2h[o] = __halves2half2(h0, h1);
            *(__half2*)&g_B2l[o] = __halves2half2(l0, l1);
        }
        for (int u = tid; u < 8192; u += 256) {
            int cL = u >> 6, r2 = (u & 63) * 2;
            float v0 = Cs[r2 * CS_PAD + cL], v1 = Cs[(r2 + 1) * CS_PAD + cL];
            size_t o = mbase + (size_t)(col0 + cL) * MM + row0 + r2;
            *(__half2*)&g_B2Th[o] = __halves2half2(__float2half_rn(v0), __float2half_rn(v1));
        }
        if (diag && tid < 128) p0 = Cs[tid * CS_PAD + tid];
    } else {
        for (int u = tid; u < 8192; u += 256) {
            int i = u >> 6, j2 = (u & 63) * 2;
            float b30 = Cs[i * CS_PAD + j2], b31 = Cs[i * CS_PAD + j2 + 1];
            size_t o = mbase + (size_t)(row0 + i) * MM + col0 + j2;
            float2 th  = __half22float2(*(const __half2*)&g_B2Th[o]);
            float2 bh2 = __half22float2(*(const __half2*)&g_B2h[o]);
            float2 bl2 = __half22float2(*(const __half2*)&g_B2l[o]);
            float t0 = th.x, t1 = th.y;                    // B2[j,i] (hi)
            float b0 = bh2.x + bl2.x, b1 = bh2.y + bl2.y;  // B2[i,j]
            p3 += b30 * t0 + b31 * t1;        // tr(A^5)
            p2 += b0 * t0 + b1 * t1;          // tr(A^4)
            if (diag) {
                if (i == j2)     p1 += b30;   // tr(A^3)
                if (i == j2 + 1) p1 += b31;
            }
        }
    }

    // deterministic block reduce
#pragma unroll
    for (int off = 16; off; off >>= 1) {
        p0 += __shfl_down_sync(0xFFFFFFFFu, p0, off);
        p1 += __shfl_down_sync(0xFFFFFFFFu, p1, off);
        p2 += __shfl_down_sync(0xFFFFFFFFu, p2, off);
        p3 += __shfl_down_sync(0xFFFFFFFFu, p3, off);
    }
    __syncthreads();
    if (lane == 0) {
        red[w * 4 + 0] = p0; red[w * 4 + 1] = p1;
        red[w * 4 + 2] = p2; red[w * 4 + 3] = p3;
    }
    __syncthreads();
    if (tid == 0) {
        float s0 = 0.f, s1 = 0.f, s2 = 0.f, s3 = 0.f;
        for (int q = 0; q < 8; q++) {
            s0 += red[q * 4]; s1 += red[q * 4 + 1];
            s2 += red[q * 4 + 2]; s3 += red[q * 4 + 3];
        }
        int slot = (bc * 4 + (int)(blockIdx.y * 2 + blockIdx.x)) * 4;
        if (!IS2) g_part[slot + 0] = s0;
        else { g_part[slot + 1] = s1; g_part[slot + 2] = s2; g_part[slot + 3] = s3; }
    }
}

// ---------------------------------------------------------------------------
// Combine: out[b] = sum coef[c,i,j] * tr_{i+2}^(j+1) / 65536^(i+j+1)
// ---------------------------------------------------------------------------
__global__ void __launch_bounds__(512) final_kernel(const float* __restrict__ coef,
                                                    float* __restrict__ out) {
    int t = threadIdx.x;
    int b = t >> 4, c = t & 15;
    int bc = b * CHN + c;
    double tr[4];
#pragma unroll
    for (int k = 0; k < 4; k++) {
        float s = 0.f;
#pragma unroll
        for (int tile = 0; tile < 4; tile++) s += g_part[(bc * 4 + tile) * 4 + k];
        tr[k] = (double)s;
    }
    double sum = 0.0;
#pragma unroll
    for (int i = 0; i < 4; i++) {
        double p = tr[i];
        double tp = p;
#pragma unroll
        for (int j = 0; j < 4; j++) {
            double v = ldexp(tp, -16 * (i + j + 1));
            sum += (double)coef[c * 16 + i * 4 + j] * v;
            tp *= p;
        }
    }
#pragma unroll
    for (int off = 8; off; off >>= 1)
        sum += __shfl_down_sync(0xFFFFFFFFu, sum, off, 16);
    if (c == 0) out[b] = (float)sum;
}

extern "C" void kernel_launch(void* const* d_in, const int* in_sizes, int n_in,
                              void* d_out, int out_size) {
    const float* x    = (const float*)d_in[0];
    const float* w    = (const float*)d_in[1];
    const float* bias = (const float*)d_in[2];
    const float* coef = (const float*)d_in[3];
    float* out = (float*)d_out;

    cudaFuncSetAttribute(gemm_kernel<false>, cudaFuncAttributeMaxDynamicSharedMemorySize, GEMM_SMEM);
    cudaFuncSetAttribute(gemm_kernel<true>,  cudaFuncAttributeMaxDynamicSharedMemorySize, GEMM_SMEM);

    conv_kernel<<<dim3(8, 8, BB), dim3(32, 8)>>>(x, w, bias);
    gemm_kernel<false><<<dim3(2, 2, NMAT), 256, GEMM_SMEM>>>();
    gemm_kernel<true> <<<dim3(2, 2, NMAT), 256, GEMM_SMEM>>>();
    final_kernel<<<1, 512>>>(coef, out);
}

// round 6
// speedup vs baseline: 2.9618x; 1.1385x over previous
#include <cuda_runtime.h>
#include <cuda_fp16.h>
#include <cstdint>

#define BB   32
#define CHN  16
#define NN   261
#define MM   256
#define MAT  (MM*MM)
#define NMAT (BB*CHN)

// ---------------- scratch (device globals; no allocs allowed) ----------------
__device__ __align__(256) __half g_Ah  [NMAT * MAT];   // feat fp16 hi (row-major)
__device__ __align__(256) __half g_Al  [NMAT * MAT];   // feat fp16 lo (row-major)
__device__ __align__(256) __half g_B2h [NMAT * MAT];   // B2 row-major hi
__device__ float g_part[NMAT * 4 * 4];   // [bc][tile 2x2][k: tr2,tr3,tr4,tr5]

// ---------------------------- helpers ---------------------------------------
__device__ __forceinline__ uint32_t smem_u32(const void* p) {
    uint32_t a;
    asm("{ .reg .u64 t; cvta.to.shared.u64 t, %1; cvt.u32.u64 %0, t; }" : "=r"(a) : "l"(p));
    return a;
}
#define CP16(dst, src) asm volatile("cp.async.cg.shared.global [%0], [%1], 16;" :: "r"((uint32_t)(dst)), "l"(src))
#define CP_COMMIT()    asm volatile("cp.async.commit_group;" ::: "memory")
#define CP_WAIT(n)     asm volatile("cp.async.wait_group %0;" :: "n"(n) : "memory")

#define MMA_F16(d, a, b) \
    asm volatile("mma.sync.aligned.m16n8k16.row.col.f32.f16.f16.f32 " \
        "{%0,%1,%2,%3},{%4,%5,%6,%7},{%8,%9},{%0,%1,%2,%3};" \
        : "+f"((d)[0]), "+f"((d)[1]), "+f"((d)[2]), "+f"((d)[3]) \
        : "r"((a)[0]), "r"((a)[1]), "r"((a)[2]), "r"((a)[3]), "r"((b)[0]), "r"((b)[1]))

#define LDSM4(r, addr) \
    asm volatile("ldmatrix.sync.aligned.m8n8.x4.shared.b16 {%0,%1,%2,%3}, [%4];" \
        : "=r"((r)[0]), "=r"((r)[1]), "=r"((r)[2]), "=r"((r)[3]) : "r"(addr))

#define LDSM4T(r, addr) \
    asm volatile("ldmatrix.sync.aligned.m8n8.x4.trans.shared.b16 {%0,%1,%2,%3}, [%4];" \
        : "=r"((r)[0]), "=r"((r)[1]), "=r"((r)[2]), "=r"((r)[3]) : "r"(addr))

__device__ __forceinline__ void split_f16(float v, __half& h, __half& l) {
    h = __float2half_rn(v);
    l = __float2half_rn(v - __half2float(h));
}

// ---------------------------------------------------------------------------
// Conv: x[b,261,261] * w[16,1,6,6] + bias -> g_Ah/g_Al (row-major only)
// ---------------------------------------------------------------------------
__global__ void __launch_bounds__(256) conv_kernel(const float* __restrict__ x,
                                                   const float* __restrict__ w,
                                                   const float* __restrict__ bias) {
    __shared__ float xs[37][38];
    __shared__ float ws[CHN * 36];
    __shared__ float bs[CHN];
    const int b  = blockIdx.z;
    const int bx = blockIdx.x * 32, by = blockIdx.y * 32;
    const int tx = threadIdx.x, ty = threadIdx.y;
    const int tid = ty * 32 + tx;

    for (int i = tid; i < 37 * 37; i += 256) {
        int r = i / 37, c = i % 37;
        xs[r][c] = x[b * NN * NN + (by + r) * NN + (bx + c)];
    }
    for (int i = tid; i < CHN * 36; i += 256) ws[i] = w[i];
    if (tid < CHN) bs[tid] = bias[tid];
    __syncthreads();

    float acc[4][CHN];
#pragma unroll
    for (int r = 0; r < 4; r++)
#pragma unroll
        for (int c = 0; c < CHN; c++) acc[r][c] = bs[c];

#pragma unroll
    for (int p = 0; p < 6; p++) {
#pragma unroll
        for (int q = 0; q < 6; q++) {
            float xv[4];
#pragma unroll
            for (int r = 0; r < 4; r++) xv[r] = xs[ty + 8 * r + p][tx + q];
#pragma unroll
            for (int c = 0; c < CHN; c++) {
                float wv = ws[c * 36 + p * 6 + q];
#pragma unroll
                for (int r = 0; r < 4; r++) acc[r][c] += xv[r] * wv;
            }
        }
    }

#pragma unroll
    for (int c = 0; c < CHN; c++) {
        size_t base = (size_t)(b * CHN + c) * MAT;
#pragma unroll
        for (int r = 0; r < 4; r++) {
            int row = by + ty + 8 * r, col = bx + tx;
            __half h, l; split_f16(acc[r][c], h, l);
            g_Ah[base + row * MM + col] = h;
            g_Al[base + row * MM + col] = l;
        }
    }
}

// ---------------------------------------------------------------------------
// fp16 mma.sync GEMM, 128x128 tile, BK=32, 3-stage cp.async ring.
// A fragments: ldmatrix (row-major A tiles, hi+lo). B fragments: ldmatrix.trans
// directly on row-major source rows (B = A for stage1, B = B2 for stage2).
// IS2=0: C = A@A  -> write B2 hi row-major + tr2 diag partial
// IS2=1: C = A@B2 (=B3, never stored) -> tr3 diag; tr4 = sum C*A^T; tr5 = sum C*B2^T
// ---------------------------------------------------------------------------
#define PADK    40                     // A halves per row (32 + 8 pad); 80B stride
#define PADN    136                    // B halves per row (128 + 8 pad); 272B stride
#define OFF_AH  0
#define OFF_AL  10240
#define OFF_B   20480
#define STAGE_B 29184                  // 2*10240 + 32*272
#define GEMM_SMEM (3 * STAGE_B)        // 87552
#define CS_PAD  129

__device__ __forceinline__ void load_stage(uint32_t st,
        const __half* __restrict__ Ah, const __half* __restrict__ Al,
        const __half* __restrict__ Bsrc, int col0, int kb, int tid) {
#pragma unroll
    for (int it = 0; it < 2; ++it) {
        int u = it * 256 + tid;          // 0..511
        int rowA = u >> 2, segA = u & 3;
        uint32_t da = (uint32_t)(rowA * (PADK * 2) + segA * 16);
        CP16(st + OFF_AH + da, Ah + rowA * MM + kb * 32 + segA * 8);
        CP16(st + OFF_AL + da, Al + rowA * MM + kb * 32 + segA * 8);
        int rowB = u >> 4, segB = u & 15;
        uint32_t db = (uint32_t)(rowB * (PADN * 2) + segB * 16);
        CP16(st + OFF_B + db, Bsrc + (size_t)(kb * 32 + rowB) * MM + col0 + segB * 8);
    }
}

template <bool IS2>
__global__ void __launch_bounds__(256) gemm_kernel() {
    extern __shared__ char sm[];
    const uint32_t sbase = smem_u32(sm);
    const int tid  = threadIdx.x;
    const int lane = tid & 31;
    const int w    = tid >> 5;
    const int wm   = w >> 2;            // 0..1 -> 64-row slab
    const int wn   = w & 3;             // 0..3 -> 32-col slab
    const int bc   = blockIdx.z;
    const int row0 = blockIdx.y * 128;
    const int col0 = blockIdx.x * 128;
    const bool diag = (blockIdx.x == blockIdx.y);
    const size_t mbase = (size_t)bc * MAT;

    const __half* Ah = g_Ah + mbase + (size_t)row0 * MM;
    const __half* Al = g_Al + mbase + (size_t)row0 * MM;
    const __half* Bsrc = (IS2 ? g_B2h : g_Ah) + mbase;   // row-major; rows = k

    // A ldmatrix lane offset (non-trans, 80B row stride) — conflict-free
    const uint32_t aRowOff = (uint32_t)(((lane & 15) * PADK + ((lane >> 4) << 3)) * 2)
                           + (uint32_t)(wm * 64 * PADK * 2);
    // B ldmatrix.trans lane offset (272B row stride) — conflict-free (4l bank rotation)
    const int krow_lane = (lane & 7) + ((lane >> 3) & 1) * 8;   // 0..15
    const int ncol_lane = (lane >> 4) * 8;                       // 0 or 8
    const uint32_t bRowOff = (uint32_t)(krow_lane * (PADN * 2)
                           + (wn * 32 + ncol_lane) * 2);

    float acc[4][4][4];
#pragma unroll
    for (int mi = 0; mi < 4; mi++)
#pragma unroll
        for (int ni = 0; ni < 4; ni++)
#pragma unroll
            for (int e = 0; e < 4; e++) acc[mi][ni][e] = 0.f;

    load_stage(sbase + 0 * STAGE_B, Ah, Al, Bsrc, col0, 0, tid);
    CP_COMMIT();
    load_stage(sbase + 1 * STAGE_B, Ah, Al, Bsrc, col0, 1, tid);
    CP_COMMIT();

    for (int kb = 0; kb < 8; ++kb) {
        if (kb < 7) { CP_WAIT(1); } else { CP_WAIT(0); }
        __syncthreads();
        if (kb + 2 < 8) {
            int s = (kb + 2) % 3;
            load_stage(sbase + s * STAGE_B, Ah, Al, Bsrc, col0, kb + 2, tid);
            CP_COMMIT();
        }

        const uint32_t st = sbase + (uint32_t)((kb % 3) * STAGE_B);
        const uint32_t aH = st + OFF_AH + aRowOff;
        const uint32_t aL = st + OFF_AL + aRowOff;
        const uint32_t bB = st + OFF_B + bRowOff;

#pragma unroll
        for (int ks = 0; ks < 2; ++ks) {
            uint32_t ah[4][4], al[4][4], bq[2][4];
#pragma unroll
            for (int mi = 0; mi < 4; mi++)
                LDSM4(ah[mi], aH + (uint32_t)(mi * 16 * PADK * 2 + ks * 32));
#pragma unroll
            for (int mi = 0; mi < 4; mi++)
                LDSM4(al[mi], aL + (uint32_t)(mi * 16 * PADK * 2 + ks * 32));
#pragma unroll
            for (int q = 0; q < 2; q++)
                LDSM4T(bq[q], bB + (uint32_t)(ks * 16 * PADN * 2 + q * 32));
#pragma unroll
            for (int mi = 0; mi < 4; mi++)
#pragma unroll
                for (int ni = 0; ni < 4; ni++) {
                    MMA_F16(acc[mi][ni], ah[mi], &bq[ni >> 1][(ni & 1) * 2]);
                    MMA_F16(acc[mi][ni], al[mi], &bq[ni >> 1][(ni & 1) * 2]);
                }
        }
    }
    __syncthreads();

    // ---------------- epilogue: stage C through smem ----------------
    float* Cs  = (float*)sm;                      // [128][129]
    float* red = (float*)(sm + 66048);
#pragma unroll
    for (int mi = 0; mi < 4; mi++)
#pragma unroll
        for (int ni = 0; ni < 4; ni++) {
            int r = wm * 64 + mi * 16 + (lane >> 2);
            int c = wn * 32 + ni * 8 + (lane & 3) * 2;
            Cs[r * CS_PAD + c]           = acc[mi][ni][0];
            Cs[r * CS_PAD + c + 1]       = acc[mi][ni][1];
            Cs[(r + 8) * CS_PAD + c]     = acc[mi][ni][2];
            Cs[(r + 8) * CS_PAD + c + 1] = acc[mi][ni][3];
        }
    __syncthreads();

    float p0 = 0.f;                     // tr2 (!IS2) or tr3 (IS2), from diag
    float p2 = 0.f, p3 = 0.f;           // tr4, tr5 (IS2 only)

    if (diag && tid < 128) p0 = Cs[tid * CS_PAD + tid];

    if (!IS2) {
        for (int u = tid; u < 8192; u += 256) {
            int i = u >> 6, j2 = (u & 63) * 2;
            float v0 = Cs[i * CS_PAD + j2], v1 = Cs[i * CS_PAD + j2 + 1];
            size_t o = mbase + (size_t)(row0 + i) * MM + col0 + j2;
            *(__half2*)&g_B2h[o] = __halves2half2(__float2half_rn(v0), __float2half_rn(v1));
        }
    } else {
        // tr4 = sum C[r][c] * A[c][r] ; tr5 = sum C[r][c] * B2[c][r]
        for (int u = tid; u < 8192; u += 256) {
            int jj = u >> 6, ii2 = (u & 63) * 2;
            size_t o = mbase + (size_t)(col0 + jj) * MM + row0 + ii2;
            float2 at = __half22float2(*(const __half2*)&g_Ah[o]);
            float2 bt = __half22float2(*(const __half2*)&g_B2h[o]);
            float c0 = Cs[ii2 * CS_PAD + jj];
            float c1 = Cs[(ii2 + 1) * CS_PAD + jj];
            p2 += c0 * at.x + c1 * at.y;      // tr(A^4)
            p3 += c0 * bt.x + c1 * bt.y;      // tr(A^5)
        }
    }

    // deterministic block reduce
#pragma unroll
    for (int off = 16; off; off >>= 1) {
        p0 += __shfl_down_sync(0xFFFFFFFFu, p0, off);
        p2 += __shfl_down_sync(0xFFFFFFFFu, p2, off);
        p3 += __shfl_down_sync(0xFFFFFFFFu, p3, off);
    }
    __syncthreads();
    if (lane == 0) {
        red[w * 3 + 0] = p0; red[w * 3 + 1] = p2; red[w * 3 + 2] = p3;
    }
    __syncthreads();
    if (tid == 0) {
        float s0 = 0.f, s2 = 0.f, s3 = 0.f;
        for (int q = 0; q < 8; q++) {
            s0 += red[q * 3]; s2 += red[q * 3 + 1]; s3 += red[q * 3 + 2];
        }
        int slot = (bc * 4 + (int)(blockIdx.y * 2 + blockIdx.x)) * 4;
        if (!IS2) g_part[slot + 0] = s0;
        else { g_part[slot + 1] = s0; g_part[slot + 2] = s2; g_part[slot + 3] = s3; }
    }
}

// ---------------------------------------------------------------------------
// Combine: out[b] = sum coef[c,i,j] * tr_{i+2}^(j+1) / 65536^(i+j+1)
// ---------------------------------------------------------------------------
__global__ void __launch_bounds__(512) final_kernel(const float* __restrict__ coef,
                                                    float* __restrict__ out) {
    int t = threadIdx.x;
    int b = t >> 4, c = t & 15;
    int bc = b * CHN + c;
    double tr[4];
#pragma unroll
    for (int k = 0; k < 4; k++) {
        float s = 0.f;
#pragma unroll
        for (int tile = 0; tile < 4; tile++) s += g_part[(bc * 4 + tile) * 4 + k];
        tr[k] = (double)s;
    }
    double sum = 0.0;
#pragma unroll
    for (int i = 0; i < 4; i++) {
        double p = tr[i];
        double tp = p;
#pragma unroll
        for (int j = 0; j < 4; j++) {
            double v = ldexp(tp, -16 * (i + j + 1));
            sum += (double)coef[c * 16 + i * 4 + j] * v;
            tp *= p;
        }
    }
#pragma unroll
    for (int off = 8; off; off >>= 1)
        sum += __shfl_down_sync(0xFFFFFFFFu, sum, off, 16);
    if (c == 0) out[b] = (float)sum;
}

extern "C" void kernel_launch(void* const* d_in, const int* in_sizes, int n_in,
                              void* d_out, int out_size) {
    const float* x    = (const float*)d_in[0];
    const float* w    = (const float*)d_in[1];
    const float* bias = (const float*)d_in[2];
    const float* coef = (const float*)d_in[3];
    float* out = (float*)d_out;

    cudaFuncSetAttribute(gemm_kernel<false>, cudaFuncAttributeMaxDynamicSharedMemorySize, GEMM_SMEM);
    cudaFuncSetAttribute(gemm_kernel<true>,  cudaFuncAttributeMaxDynamicSharedMemorySize, GEMM_SMEM);

    conv_kernel<<<dim3(8, 8, BB), dim3(32, 8)>>>(x, w, bias);
    gemm_kernel<false><<<dim3(2, 2, NMAT), 256, GEMM_SMEM>>>();
    gemm_kernel<true> <<<dim3(2, 2, NMAT), 256, GEMM_SMEM>>>();
    final_kernel<<<1, 512>>>(coef, out);
}